// round 14
// baseline (speedup 1.0000x reference)
#include <cuda_runtime.h>
#include <cuda_bf16.h>
#include <math.h>
#include <stdint.h>

#define NN   100000
#define EE   1600000
#define ET   1700000      // EE + NN self loops
#define FIN  512
#define HD   64           // H1*D1
#define H1   8
#define D1   8
#define CC   16
#define NB   ((NN + 255) / 256)   // 391 scan blocks

// ---------------- scratch (static device memory; no allocations) ----------------
__device__ int   g_flag;
__device__ int   g_src[ET];
__device__ int   g_dst[ET];
__device__ int   g_col[ET];
__device__ int   g_counts[NN];
__device__ int   g_cursor[NN];
__device__ int   g_rowptr[NN + 1];
__device__ int   g_bsum[NB];
__device__ int   g_boff[NB];
// W1^T in mma-fragment order with K-permutation: [n][ks][tc] uint4 =
// {hi(kp,kp+1), hi(kp+2,kp+3), lo(kp,kp+1), lo(kp+2,kp+3)}, kp = ks*16 + tc*4
__device__ uint4 g_wfrag[HD * 32 * 4];
__device__ float g_h1[(size_t)NN * HD];
__device__ float g_es1[(size_t)NN * H1];
__device__ float g_ed1[(size_t)NN * H1];
__device__ float g_h2[(size_t)NN * CC];
__device__ float g_es2[NN];
__device__ float g_ed2[NN];

__device__ __forceinline__ uint32_t pack_hi(float v0, float v1) {
    __nv_bfloat16 h0 = __float2bfloat16_rn(v0);
    __nv_bfloat16 h1 = __float2bfloat16_rn(v1);
    return ((uint32_t)__bfloat16_as_ushort(h1) << 16) | __bfloat16_as_ushort(h0);
}
__device__ __forceinline__ uint32_t pack_lo(float v0, float v1) {
    __nv_bfloat16 h0 = __float2bfloat16_rn(v0);
    __nv_bfloat16 h1 = __float2bfloat16_rn(v1);
    __nv_bfloat16 l0 = __float2bfloat16_rn(v0 - __bfloat162float(h0));
    __nv_bfloat16 l1 = __float2bfloat16_rn(v1 - __bfloat162float(h1));
    return ((uint32_t)__bfloat16_as_ushort(l1) << 16) | __bfloat16_as_ushort(l0);
}

// ---------------- init: zero counts + dtype detect + W1 fragment-order convert ----------------
__global__ __launch_bounds__(256) void init_kernel(const int* ei32, const float* __restrict__ W1) {
    int i = blockIdx.x * blockDim.x + threadIdx.x;
    if (i < NN) g_counts[i] = 0;
    if (i < HD * 32 * 4) {                  // 8192 fragments
        int n = i >> 7, ks = (i >> 2) & 31, tc = i & 3;
        int kp = ks * 16 + tc * 4;          // physical k base (K-permuted order)
        float v0 = W1[(size_t)kp * HD + n];
        float v1 = W1[(size_t)(kp + 1) * HD + n];
        float v2 = W1[(size_t)(kp + 2) * HD + n];
        float v3 = W1[(size_t)(kp + 3) * HD + n];
        uint4 w;
        w.x = pack_hi(v0, v1);
        w.y = pack_hi(v2, v3);
        w.z = pack_lo(v0, v1);
        w.w = pack_lo(v2, v3);
        g_wfrag[i] = w;
    }
    if (blockIdx.x == 0 && threadIdx.x < 32) {
        int lane = threadIdx.x;
        int bad = 0;
        for (int j = lane; j < 256; j += 32) {
            int k = j * 6250;
            if (ei32[2 * k + 1] != 0) bad = 1;
        }
        unsigned b = __ballot_sync(0xffffffffu, bad);
        if (lane == 0) g_flag = (b == 0) ? 1 : 0;
    }
}

// ---------------- convert + histogram in one edge pass ----------------
__global__ __launch_bounds__(256) void convert_hist_kernel(const void* ei) {
    int e = blockIdx.x * blockDim.x + threadIdx.x;
    if (e >= ET) return;
    int s, d;
    if (e < EE) {
        if (g_flag) {
            const long long* p = (const long long*)ei;
            s = (int)p[e]; d = (int)p[EE + e];
        } else {
            const int* p = (const int*)ei;
            s = p[e]; d = p[EE + e];
        }
    } else {
        s = e - EE; d = e - EE;
    }
    g_src[e] = s; g_dst[e] = d;
    atomicAdd(&g_counts[d], 1);
}

// ---------------- parallel scan ----------------
__global__ __launch_bounds__(256) void scan_partial_kernel() {
    __shared__ int wsum[8];
    int t = threadIdx.x;
    int i = blockIdx.x * 256 + t;
    int c = (i < NN) ? g_counts[i] : 0;
    int v = c;
    #pragma unroll
    for (int off = 1; off < 32; off <<= 1) v += __shfl_xor_sync(0xffffffffu, v, off);
    if ((t & 31) == 0) wsum[t >> 5] = v;
    __syncthreads();
    if (t == 0) {
        int s = 0;
        #pragma unroll
        for (int w = 0; w < 8; w++) s += wsum[w];
        g_bsum[blockIdx.x] = s;
    }
}

__global__ __launch_bounds__(512) void scan_blocks_kernel() {
    __shared__ int sh[512];
    int t = threadIdx.x;
    sh[t] = (t < NB) ? g_bsum[t] : 0;
    __syncthreads();
    for (int off = 1; off < 512; off <<= 1) {
        int v = (t >= off) ? sh[t - off] : 0;
        __syncthreads();
        sh[t] += v;
        __syncthreads();
    }
    if (t < NB) g_boff[t] = (t == 0) ? 0 : sh[t - 1];
}

__global__ __launch_bounds__(256) void scan_apply_kernel() {
    __shared__ int woff[8];
    int t = threadIdx.x, lane = t & 31, wid = t >> 5;
    int i = blockIdx.x * 256 + t;
    int c = (i < NN) ? g_counts[i] : 0;
    int incl = c;
    #pragma unroll
    for (int off = 1; off < 32; off <<= 1) {
        int v = __shfl_up_sync(0xffffffffu, incl, off);
        if (lane >= off) incl += v;
    }
    if (lane == 31) woff[wid] = incl;
    __syncthreads();
    if (t == 0) {
        int run = 0;
        #pragma unroll
        for (int w = 0; w < 8; w++) { int v = woff[w]; woff[w] = run; run += v; }
    }
    __syncthreads();
    int excl = incl - c + woff[wid] + g_boff[blockIdx.x];
    if (i < NN) { g_rowptr[i] = excl; g_cursor[i] = excl; }
    if (i == NN - 1) g_rowptr[NN] = ET;
}

__global__ __launch_bounds__(256) void scatter_kernel() {
    int e = blockIdx.x * blockDim.x + threadIdx.x;
    if (e < ET) {
        int d = g_dst[e];
        int pos = atomicAdd(&g_cursor[d], 1);
        g_col[pos] = g_src[e];
    }
}

// ---------------- GEMM1: cp.async-staged A + HMMA split-bf16 (K-permuted, 8x1 warp layout) ----------------
#define BKG   32                  // K per stage
#define NSTG  4                   // stages
#define ASTR  48                  // fp32 stride per A row
#define STAGE_B (128 * ASTR * 4)  // 24576 bytes
#define G1_SMEM (NSTG * STAGE_B)  // 98304 bytes

__device__ __forceinline__ void cp_async_cg(uint32_t saddr, const void* gptr, int srcsz) {
    asm volatile("cp.async.cg.shared.global [%0], [%1], 16, %2;"
                 :: "r"(saddr), "l"(gptr), "r"(srcsz));
}
__device__ __forceinline__ void cp_commit() { asm volatile("cp.async.commit_group;"); }

__device__ __forceinline__ void cvt_pair(float vx, float vy, uint32_t& hi, uint32_t& lo) {
    asm("cvt.rn.bf16x2.f32 %0, %1, %2;" : "=r"(hi) : "f"(vy), "f"(vx));
    float h0 = __uint_as_float(hi << 16);
    float h1 = __uint_as_float(hi & 0xFFFF0000u);
    float r0 = vx - h0, r1 = vy - h1;
    asm("cvt.rn.bf16x2.f32 %0, %1, %2;" : "=r"(lo) : "f"(r1), "f"(r0));
}

__device__ __forceinline__ void mma16816(float* c, const uint32_t* a, uint32_t b0, uint32_t b1) {
    asm volatile(
        "mma.sync.aligned.m16n8k16.row.col.f32.bf16.bf16.f32 "
        "{%0,%1,%2,%3}, {%4,%5,%6,%7}, {%8,%9}, {%0,%1,%2,%3};"
        : "+f"(c[0]), "+f"(c[1]), "+f"(c[2]), "+f"(c[3])
        : "r"(a[0]), "r"(a[1]), "r"(a[2]), "r"(a[3]), "r"(b0), "r"(b1));
}

__global__ __launch_bounds__(256, 2) void gemm1_mma_kernel(const float* __restrict__ x,
                                                           const float* __restrict__ a1s,
                                                           const float* __restrict__ a1d) {
    extern __shared__ float sA[];           // [NSTG][128][ASTR]
    uint32_t sbase;
    asm("{ .reg .u64 t; cvta.to.shared.u64 t, %1; cvt.u32.u64 %0, t; }" : "=r"(sbase) : "l"(sA));

    int tid = threadIdx.x;
    int wid = tid >> 5, lane = tid & 31;
    int g = lane >> 2, tc = lane & 3;
    int block_row = blockIdx.x * 128;
    int row_base = block_row + wid * 16;    // warp handles 16 rows, all 64 cols

    float acc[8][4];
    #pragma unroll
    for (int nt = 0; nt < 8; nt++)
        #pragma unroll
        for (int q = 0; q < 4; q++) acc[nt][q] = 0.f;

    const int NSTEP = FIN / BKG;            // 16

    #pragma unroll
    for (int s = 0; s < NSTG - 1; s++) {    // prologue: 3 stages
        #pragma unroll
        for (int i = 0; i < 4; i++) {
            int idx = tid + 256 * i;
            int row = idx >> 3, c4 = idx & 7;
            int grow = block_row + row;
            uint32_t sa = sbase + (uint32_t)s * STAGE_B + (row * ASTR + c4 * 4) * 4;
            cp_async_cg(sa, x + (size_t)grow * FIN + s * BKG + c4 * 4,
                        (grow < NN) ? 16 : 0);
        }
        cp_commit();
    }

    for (int step = 0; step < NSTEP; step++) {
        int rem = NSTEP - 1 - step;
        if (rem >= 2) { asm volatile("cp.async.wait_group 2;"); }
        else if (rem == 1) { asm volatile("cp.async.wait_group 1;"); }
        else { asm volatile("cp.async.wait_group 0;"); }
        __syncthreads();

        int nxt = step + NSTG - 1;
        if (nxt < NSTEP) {
            int sbuf = nxt & (NSTG - 1);
            #pragma unroll
            for (int i = 0; i < 4; i++) {
                int idx = tid + 256 * i;
                int row = idx >> 3, c4 = idx & 7;
                int grow = block_row + row;
                uint32_t sa = sbase + (uint32_t)sbuf * STAGE_B + (row * ASTR + c4 * 4) * 4;
                cp_async_cg(sa, x + (size_t)grow * FIN + nxt * BKG + c4 * 4,
                            (grow < NN) ? 16 : 0);
            }
            cp_commit();
        }

        const float* sAc = sA + (step & (NSTG - 1)) * 128 * ASTR;
        #pragma unroll
        for (int ks = 0; ks < BKG / 16; ks++) {  // 2
            int ksg = step * 2 + ks;            // global 16-k step index (0..31)
            int kl = ks * 16 + tc * 4;          // physical k base for this thread
            int lr0 = wid * 16 + g;
            int lr1 = lr0 + 8;
            float4 v0 = *(const float4*)(sAc + lr0 * ASTR + kl);
            float4 v1 = *(const float4*)(sAc + lr1 * ASTR + kl);
            uint32_t ah[4], al[4];
            cvt_pair(v0.x, v0.y, ah[0], al[0]);
            cvt_pair(v1.x, v1.y, ah[1], al[1]);
            cvt_pair(v0.z, v0.w, ah[2], al[2]);
            cvt_pair(v1.z, v1.w, ah[3], al[3]);
            #pragma unroll
            for (int nt = 0; nt < 8; nt++) {
                int n = nt * 8 + g;
                uint4 w = g_wfrag[(n * 32 + ksg) * 4 + tc];   // 1 LDG.128
                mma16816(acc[nt], ah, w.x, w.y);
                mma16816(acc[nt], al, w.x, w.y);
                mma16816(acc[nt], ah, w.z, w.w);
            }
        }
    }

    // ---- epilogue: write h1, fused es1/ed1 (head = nt) ----
    int r0 = row_base + g;
    int r1 = r0 + 8;
    #pragma unroll
    for (int nt = 0; nt < 8; nt++) {
        int col = nt * 8 + tc * 2;
        float* c = acc[nt];
        if (r0 < NN) *(float2*)(g_h1 + (size_t)r0 * HD + col) = make_float2(c[0], c[1]);
        if (r1 < NN) *(float2*)(g_h1 + (size_t)r1 * HD + col) = make_float2(c[2], c[3]);
        float as0 = a1s[nt * 8 + tc * 2], as1 = a1s[nt * 8 + tc * 2 + 1];
        float ad0 = a1d[nt * 8 + tc * 2], ad1 = a1d[nt * 8 + tc * 2 + 1];
        float es_a = c[0] * as0 + c[1] * as1;
        float ed_a = c[0] * ad0 + c[1] * ad1;
        float es_b = c[2] * as0 + c[3] * as1;
        float ed_b = c[2] * ad0 + c[3] * ad1;
        es_a += __shfl_xor_sync(0xffffffffu, es_a, 1); es_a += __shfl_xor_sync(0xffffffffu, es_a, 2);
        ed_a += __shfl_xor_sync(0xffffffffu, ed_a, 1); ed_a += __shfl_xor_sync(0xffffffffu, ed_a, 2);
        es_b += __shfl_xor_sync(0xffffffffu, es_b, 1); es_b += __shfl_xor_sync(0xffffffffu, es_b, 2);
        ed_b += __shfl_xor_sync(0xffffffffu, ed_b, 1); ed_b += __shfl_xor_sync(0xffffffffu, ed_b, 2);
        if (tc == 0) {
            if (r0 < NN) { g_es1[(size_t)r0 * H1 + nt] = es_a; g_ed1[(size_t)r0 * H1 + nt] = ed_a; }
            if (r1 < NN) { g_es1[(size_t)r1 * H1 + nt] = es_b; g_ed1[(size_t)r1 * H1 + nt] = ed_b; }
        }
    }
}

// ---------------- fused agg1 + gemm2 + es2/ed2 ----------------
// Block = 8 warps = 8 consecutive dsts. h1act lives only in smem.
__global__ __launch_bounds__(256) void agg1_gemm2_kernel(const float* __restrict__ W2,
                                                         const float* __restrict__ a2s,
                                                         const float* __restrict__ a2d) {
    __shared__ float h1s[8][64];
    __shared__ float Wst[16][68];       // W2 transposed [c][j], padded
    __shared__ float sa2s[CC], sa2d[CC];
    int tid = threadIdx.x, wid = tid >> 5, lane = tid & 31;
    {
        // load W2 (64x16) transposed: thread loads one float4 (4 consecutive c of row j)
        float4 v = ((const float4*)W2)[tid];   // j = tid>>2, c0 = (tid&3)*4
        int j = tid >> 2, c0 = (tid & 3) * 4;
        Wst[c0 + 0][j] = v.x; Wst[c0 + 1][j] = v.y;
        Wst[c0 + 2][j] = v.z; Wst[c0 + 3][j] = v.w;
        if (tid < CC) { sa2s[tid] = a2s[tid]; sa2d[tid] = a2d[tid]; }
    }

    int dst = blockIdx.x * 8 + wid;         // grid = NN/8 exactly
    int myhead = lane >> 2;
    float edv = g_ed1[(size_t)dst * H1 + myhead];
    float m = -INFINITY, s = 0.f;
    float acc0 = 0.f, acc1 = 0.f;
    int beg = g_rowptr[dst], end = g_rowptr[dst + 1];   // >=1 edge (self loop)
    int s0 = g_col[beg];
    int s1 = (beg + 1 < end) ? g_col[beg + 1] : s0;
    float es_c = g_es1[(size_t)s0 * H1 + myhead];
    float2 hv_c = *(const float2*)(g_h1 + (size_t)s0 * HD + lane * 2);
    for (int e = beg; e < end; e++) {
        int s2 = (e + 2 < end) ? g_col[e + 2] : s1;
        float es_n = g_es1[(size_t)s1 * H1 + myhead];
        float2 hv_n = *(const float2*)(g_h1 + (size_t)s1 * HD + lane * 2);
        float ev = es_c + edv;
        ev = ev > 0.f ? ev : 0.2f * ev;
        float nm = fmaxf(m, ev);
        float sc = __expf(m - nm);
        float w  = __expf(ev - nm);
        m = nm;
        s = s * sc + w;
        acc0 = acc0 * sc + hv_c.x * w;
        acc1 = acc1 * sc + hv_c.y * w;
        es_c = es_n; hv_c = hv_n;
        s1 = s2;
    }
    float o0 = acc0 / s;
    float o1 = acc1 / s;
    o0 = o0 > 0.f ? o0 : expm1f(o0);        // ELU
    o1 = o1 > 0.f ? o1 : expm1f(o1);
    h1s[wid][lane * 2] = o0;
    h1s[wid][lane * 2 + 1] = o1;
    __syncthreads();

    // gemm2 for the block's 8 rows: 8 x 64 @ 64 x 16
    if (tid < 128) {
        int nl = tid >> 4, c = tid & 15;
        int n = blockIdx.x * 8 + nl;
        float sum = 0.f;
        #pragma unroll
        for (int j4 = 0; j4 < 16; j4++) {
            float4 hv = *(const float4*)&h1s[nl][j4 * 4];
            float4 wv = *(const float4*)&Wst[c][j4 * 4];
            sum += hv.x * wv.x + hv.y * wv.y + hv.z * wv.z + hv.w * wv.w;
        }
        g_h2[(size_t)n * CC + c] = sum;
        float es = sum * sa2s[c];
        float ed = sum * sa2d[c];
        #pragma unroll
        for (int off = 1; off < 16; off <<= 1) {
            es += __shfl_xor_sync(0xffffffffu, es, off, 16);
            ed += __shfl_xor_sync(0xffffffffu, ed, off, 16);
        }
        if (c == 0) { g_es2[n] = es; g_ed2[n] = ed; }
    }
}

// ---------------- layer-2 aggregation + log_softmax : half-warp/dst, depth-2 prefetch ----------------
__global__ __launch_bounds__(256) void agg2_kernel(float* __restrict__ out) {
    int gw = (blockIdx.x * blockDim.x + threadIdx.x) >> 5;
    int lane = threadIdx.x & 31;
    int half = lane >> 4;
    int r = lane & 15;
    int dst = gw * 2 + half;
    float edv = g_ed2[dst];
    float m = -INFINITY, s = 0.f, acc = 0.f;
    int beg = g_rowptr[dst], end = g_rowptr[dst + 1];
    int s0 = g_col[beg];
    int s1 = (beg + 1 < end) ? g_col[beg + 1] : s0;
    float es_c = g_es2[s0];
    float hv_c = g_h2[(size_t)s0 * CC + r];
    for (int e = beg; e < end; e++) {
        int s2 = (e + 2 < end) ? g_col[e + 2] : s1;
        float es_n = g_es2[s1];
        float hv_n = g_h2[(size_t)s1 * CC + r];
        float ev = es_c + edv;
        ev = ev > 0.f ? ev : 0.2f * ev;
        float nm = fmaxf(m, ev);
        float sc = __expf(m - nm);
        float w  = __expf(ev - nm);
        m = nm;
        s = s * sc + w;
        acc = acc * sc + hv_c * w;
        es_c = es_n; hv_c = hv_n;
        s1 = s2;
    }
    float o = acc / s;
    float mx = o;
    #pragma unroll
    for (int off = 8; off; off >>= 1)
        mx = fmaxf(mx, __shfl_xor_sync(0xffffffffu, mx, off, 16));
    float se = __expf(o - mx);
    #pragma unroll
    for (int off = 8; off; off >>= 1)
        se += __shfl_xor_sync(0xffffffffu, se, off, 16);
    out[(size_t)dst * CC + r] = o - mx - logf(se);
}

// ---------------- launch ----------------
extern "C" void kernel_launch(void* const* d_in, const int* in_sizes, int n_in,
                              void* d_out, int out_size) {
    const float* x    = (const float*)d_in[0];
    const void*  ei   = d_in[1];
    const float* W1   = (const float*)d_in[2];
    const float* a1s  = (const float*)d_in[3];
    const float* a1d  = (const float*)d_in[4];
    const float* W2   = (const float*)d_in[5];
    const float* a2s  = (const float*)d_in[6];
    const float* a2d  = (const float*)d_in[7];
    float* out = (float*)d_out;

    cudaFuncSetAttribute(gemm1_mma_kernel, cudaFuncAttributeMaxDynamicSharedMemorySize, G1_SMEM);

    // launch order keeps gemm1 at #4 (the launch ncu captures)
    init_kernel<<<NB, 256>>>((const int*)ei, W1);
    convert_hist_kernel<<<(ET + 255) / 256, 256>>>(ei);
    scan_partial_kernel<<<NB, 256>>>();
    gemm1_mma_kernel<<<(NN + 127) / 128, 256, G1_SMEM>>>(x, a1s, a1d);   // launch #4
    scan_blocks_kernel<<<1, 512>>>();
    scan_apply_kernel<<<NB, 256>>>();
    scatter_kernel<<<(ET + 255) / 256, 256>>>();

    agg1_gemm2_kernel<<<NN / 8, 256>>>(W2, a2s, a2d);
    agg2_kernel<<<(NN * 16 + 255) / 256, 256>>>(out);
}

// round 15
// speedup vs baseline: 1.1555x; 1.1555x over previous
#include <cuda_runtime.h>
#include <cuda_bf16.h>
#include <math.h>
#include <stdint.h>

#define NN   100000
#define EE   1600000
#define ET   1700000      // EE + NN self loops
#define FIN  512
#define HD   64           // H1*D1
#define H1   8
#define D1   8
#define CC   16
#define NB   ((NN + 255) / 256)   // 391 scan blocks

// ---------------- scratch (static device memory; no allocations) ----------------
__device__ int   g_flag;
__device__ int   g_src[ET];
__device__ int   g_dst[ET];
__device__ int   g_col[ET];
__device__ int   g_counts[NN];
__device__ int   g_cursor[NN];
__device__ int   g_rowptr[NN + 1];
__device__ int   g_bsum[NB];
__device__ int   g_boff[NB];
// W1^T in mma-fragment order with K-permutation: [n][ks][tc] uint4 =
// {hi(kp,kp+1), hi(kp+2,kp+3), lo(kp,kp+1), lo(kp+2,kp+3)}, kp = ks*16 + tc*4
__device__ uint4 g_wfrag[HD * 32 * 4];
__device__ float g_h1[(size_t)NN * HD];
__device__ float g_es1[(size_t)NN * H1];
__device__ float g_ed1[(size_t)NN * H1];
__device__ float g_h2[(size_t)NN * CC];
__device__ float g_es2[NN];
__device__ float g_ed2[NN];

__device__ __forceinline__ uint32_t pack_hi(float v0, float v1) {
    __nv_bfloat16 h0 = __float2bfloat16_rn(v0);
    __nv_bfloat16 h1 = __float2bfloat16_rn(v1);
    return ((uint32_t)__bfloat16_as_ushort(h1) << 16) | __bfloat16_as_ushort(h0);
}
__device__ __forceinline__ uint32_t pack_lo(float v0, float v1) {
    __nv_bfloat16 h0 = __float2bfloat16_rn(v0);
    __nv_bfloat16 h1 = __float2bfloat16_rn(v1);
    __nv_bfloat16 l0 = __float2bfloat16_rn(v0 - __bfloat162float(h0));
    __nv_bfloat16 l1 = __float2bfloat16_rn(v1 - __bfloat162float(h1));
    return ((uint32_t)__bfloat16_as_ushort(l1) << 16) | __bfloat16_as_ushort(l0);
}

// ---------------- init: zero counts + dtype detect + W1 fragment-order convert ----------------
__global__ __launch_bounds__(256) void init_kernel(const int* ei32, const float* __restrict__ W1) {
    int i = blockIdx.x * blockDim.x + threadIdx.x;
    if (i < NN) g_counts[i] = 0;
    if (i < HD * 32 * 4) {                  // 8192 fragments
        int n = i >> 7, ks = (i >> 2) & 31, tc = i & 3;
        int kp = ks * 16 + tc * 4;          // physical k base (K-permuted order)
        float v0 = W1[(size_t)kp * HD + n];
        float v1 = W1[(size_t)(kp + 1) * HD + n];
        float v2 = W1[(size_t)(kp + 2) * HD + n];
        float v3 = W1[(size_t)(kp + 3) * HD + n];
        uint4 w;
        w.x = pack_hi(v0, v1);
        w.y = pack_hi(v2, v3);
        w.z = pack_lo(v0, v1);
        w.w = pack_lo(v2, v3);
        g_wfrag[i] = w;
    }
    if (blockIdx.x == 0 && threadIdx.x < 32) {
        int lane = threadIdx.x;
        int bad = 0;
        for (int j = lane; j < 256; j += 32) {
            int k = j * 6250;
            if (ei32[2 * k + 1] != 0) bad = 1;
        }
        unsigned b = __ballot_sync(0xffffffffu, bad);
        if (lane == 0) g_flag = (b == 0) ? 1 : 0;
    }
}

// ---------------- convert + histogram in one edge pass ----------------
__global__ __launch_bounds__(256) void convert_hist_kernel(const void* ei) {
    int e = blockIdx.x * blockDim.x + threadIdx.x;
    if (e >= ET) return;
    int s, d;
    if (e < EE) {
        if (g_flag) {
            const long long* p = (const long long*)ei;
            s = (int)p[e]; d = (int)p[EE + e];
        } else {
            const int* p = (const int*)ei;
            s = p[e]; d = p[EE + e];
        }
    } else {
        s = e - EE; d = e - EE;
    }
    g_src[e] = s; g_dst[e] = d;
    atomicAdd(&g_counts[d], 1);
}

// ---------------- parallel scan ----------------
__global__ __launch_bounds__(256) void scan_partial_kernel() {
    __shared__ int wsum[8];
    int t = threadIdx.x;
    int i = blockIdx.x * 256 + t;
    int c = (i < NN) ? g_counts[i] : 0;
    int v = c;
    #pragma unroll
    for (int off = 1; off < 32; off <<= 1) v += __shfl_xor_sync(0xffffffffu, v, off);
    if ((t & 31) == 0) wsum[t >> 5] = v;
    __syncthreads();
    if (t == 0) {
        int s = 0;
        #pragma unroll
        for (int w = 0; w < 8; w++) s += wsum[w];
        g_bsum[blockIdx.x] = s;
    }
}

__global__ __launch_bounds__(512) void scan_blocks_kernel() {
    __shared__ int sh[512];
    int t = threadIdx.x;
    sh[t] = (t < NB) ? g_bsum[t] : 0;
    __syncthreads();
    for (int off = 1; off < 512; off <<= 1) {
        int v = (t >= off) ? sh[t - off] : 0;
        __syncthreads();
        sh[t] += v;
        __syncthreads();
    }
    if (t < NB) g_boff[t] = (t == 0) ? 0 : sh[t - 1];
}

__global__ __launch_bounds__(256) void scan_apply_kernel() {
    __shared__ int woff[8];
    int t = threadIdx.x, lane = t & 31, wid = t >> 5;
    int i = blockIdx.x * 256 + t;
    int c = (i < NN) ? g_counts[i] : 0;
    int incl = c;
    #pragma unroll
    for (int off = 1; off < 32; off <<= 1) {
        int v = __shfl_up_sync(0xffffffffu, incl, off);
        if (lane >= off) incl += v;
    }
    if (lane == 31) woff[wid] = incl;
    __syncthreads();
    if (t == 0) {
        int run = 0;
        #pragma unroll
        for (int w = 0; w < 8; w++) { int v = woff[w]; woff[w] = run; run += v; }
    }
    __syncthreads();
    int excl = incl - c + woff[wid] + g_boff[blockIdx.x];
    if (i < NN) { g_rowptr[i] = excl; g_cursor[i] = excl; }
    if (i == NN - 1) g_rowptr[NN] = ET;
}

__global__ __launch_bounds__(256) void scatter_kernel() {
    int e = blockIdx.x * blockDim.x + threadIdx.x;
    if (e < ET) {
        int d = g_dst[e];
        int pos = atomicAdd(&g_cursor[d], 1);
        g_col[pos] = g_src[e];
    }
}

// ---------------- GEMM1: cp.async-staged A + HMMA split-bf16 (K-permuted, 4x2 layout) ----------------
#define BKG   32                  // K per stage
#define NSTG  4                   // stages
#define ASTR  48                  // fp32 stride per A row
#define STAGE_B (128 * ASTR * 4)  // 24576 bytes
#define G1_SMEM (NSTG * STAGE_B)  // 98304 bytes

__device__ __forceinline__ void cp_async_cg(uint32_t saddr, const void* gptr, int srcsz) {
    asm volatile("cp.async.cg.shared.global [%0], [%1], 16, %2;"
                 :: "r"(saddr), "l"(gptr), "r"(srcsz));
}
__device__ __forceinline__ void cp_commit() { asm volatile("cp.async.commit_group;"); }

__device__ __forceinline__ void cvt_pair(float vx, float vy, uint32_t& hi, uint32_t& lo) {
    asm("cvt.rn.bf16x2.f32 %0, %1, %2;" : "=r"(hi) : "f"(vy), "f"(vx));
    float h0 = __uint_as_float(hi << 16);
    float h1 = __uint_as_float(hi & 0xFFFF0000u);
    float r0 = vx - h0, r1 = vy - h1;
    asm("cvt.rn.bf16x2.f32 %0, %1, %2;" : "=r"(lo) : "f"(r1), "f"(r0));
}

__device__ __forceinline__ void mma16816(float* c, const uint32_t* a, uint32_t b0, uint32_t b1) {
    asm volatile(
        "mma.sync.aligned.m16n8k16.row.col.f32.bf16.bf16.f32 "
        "{%0,%1,%2,%3}, {%4,%5,%6,%7}, {%8,%9}, {%0,%1,%2,%3};"
        : "+f"(c[0]), "+f"(c[1]), "+f"(c[2]), "+f"(c[3])
        : "r"(a[0]), "r"(a[1]), "r"(a[2]), "r"(a[3]), "r"(b0), "r"(b1));
}

__global__ __launch_bounds__(256, 2) void gemm1_mma_kernel(const float* __restrict__ x,
                                                           const float* __restrict__ a1s,
                                                           const float* __restrict__ a1d) {
    extern __shared__ float sA[];           // [NSTG][128][ASTR]
    uint32_t sbase;
    asm("{ .reg .u64 t; cvta.to.shared.u64 t, %1; cvt.u32.u64 %0, t; }" : "=r"(sbase) : "l"(sA));

    int tid = threadIdx.x;
    int wid = tid >> 5, lane = tid & 31;
    int g = lane >> 2, tc = lane & 3;
    int wm = wid & 3, wn = wid >> 2;
    int block_row = blockIdx.x * 128;
    int row_base = block_row + wm * 32;

    float acc[2][4][4];
    #pragma unroll
    for (int mt = 0; mt < 2; mt++)
        #pragma unroll
        for (int nt = 0; nt < 4; nt++)
            #pragma unroll
            for (int q = 0; q < 4; q++) acc[mt][nt][q] = 0.f;

    const int NSTEP = FIN / BKG;            // 16

    #pragma unroll
    for (int s = 0; s < NSTG - 1; s++) {    // prologue: 3 stages
        #pragma unroll
        for (int i = 0; i < 4; i++) {
            int idx = tid + 256 * i;
            int row = idx >> 3, c4 = idx & 7;
            int grow = block_row + row;
            uint32_t sa = sbase + (uint32_t)s * STAGE_B + (row * ASTR + c4 * 4) * 4;
            cp_async_cg(sa, x + (size_t)grow * FIN + s * BKG + c4 * 4,
                        (grow < NN) ? 16 : 0);
        }
        cp_commit();
    }

    for (int step = 0; step < NSTEP; step++) {
        int rem = NSTEP - 1 - step;
        if (rem >= 2) { asm volatile("cp.async.wait_group 2;"); }
        else if (rem == 1) { asm volatile("cp.async.wait_group 1;"); }
        else { asm volatile("cp.async.wait_group 0;"); }
        __syncthreads();

        int nxt = step + NSTG - 1;
        if (nxt < NSTEP) {
            int sbuf = nxt & (NSTG - 1);
            #pragma unroll
            for (int i = 0; i < 4; i++) {
                int idx = tid + 256 * i;
                int row = idx >> 3, c4 = idx & 7;
                int grow = block_row + row;
                uint32_t sa = sbase + (uint32_t)sbuf * STAGE_B + (row * ASTR + c4 * 4) * 4;
                cp_async_cg(sa, x + (size_t)grow * FIN + nxt * BKG + c4 * 4,
                            (grow < NN) ? 16 : 0);
            }
            cp_commit();
        }

        const float* sAc = sA + (step & (NSTG - 1)) * 128 * ASTR;
        #pragma unroll
        for (int ks = 0; ks < BKG / 16; ks++) {  // 2
            int ksg = step * 2 + ks;            // global 16-k step index (0..31)
            int kl = ks * 16 + tc * 4;          // physical k base for this thread
            uint32_t ah[2][4], al[2][4];
            #pragma unroll
            for (int mt = 0; mt < 2; mt++) {
                int lr0 = wm * 32 + mt * 16 + g;
                int lr1 = lr0 + 8;
                float4 v0 = *(const float4*)(sAc + lr0 * ASTR + kl);
                float4 v1 = *(const float4*)(sAc + lr1 * ASTR + kl);
                cvt_pair(v0.x, v0.y, ah[mt][0], al[mt][0]);
                cvt_pair(v1.x, v1.y, ah[mt][1], al[mt][1]);
                cvt_pair(v0.z, v0.w, ah[mt][2], al[mt][2]);
                cvt_pair(v1.z, v1.w, ah[mt][3], al[mt][3]);
            }
            #pragma unroll
            for (int nt = 0; nt < 4; nt++) {
                int n = wn * 32 + nt * 8 + g;
                uint4 w = g_wfrag[(n * 32 + ksg) * 4 + tc];   // 1 LDG.128
                #pragma unroll
                for (int mt = 0; mt < 2; mt++) {
                    mma16816(acc[mt][nt], ah[mt], w.x, w.y);
                    mma16816(acc[mt][nt], al[mt], w.x, w.y);
                    mma16816(acc[mt][nt], ah[mt], w.z, w.w);
                }
            }
        }
    }

    // ---- epilogue: write h1, fused es/ed ----
    int col_base = wn * 32;
    #pragma unroll
    for (int mt = 0; mt < 2; mt++) {
        int r0 = row_base + mt * 16 + g;
        int r1 = r0 + 8;
        #pragma unroll
        for (int nt = 0; nt < 4; nt++) {
            int col = col_base + nt * 8 + tc * 2;
            float* c = acc[mt][nt];
            if (r0 < NN) *(float2*)(g_h1 + (size_t)r0 * HD + col) = make_float2(c[0], c[1]);
            if (r1 < NN) *(float2*)(g_h1 + (size_t)r1 * HD + col) = make_float2(c[2], c[3]);
            int head = (col_base >> 3) + nt;
            float as0 = a1s[head * 8 + tc * 2], as1 = a1s[head * 8 + tc * 2 + 1];
            float ad0 = a1d[head * 8 + tc * 2], ad1 = a1d[head * 8 + tc * 2 + 1];
            float es_a = c[0] * as0 + c[1] * as1;
            float ed_a = c[0] * ad0 + c[1] * ad1;
            float es_b = c[2] * as0 + c[3] * as1;
            float ed_b = c[2] * ad0 + c[3] * ad1;
            es_a += __shfl_xor_sync(0xffffffffu, es_a, 1); es_a += __shfl_xor_sync(0xffffffffu, es_a, 2);
            ed_a += __shfl_xor_sync(0xffffffffu, ed_a, 1); ed_a += __shfl_xor_sync(0xffffffffu, ed_a, 2);
            es_b += __shfl_xor_sync(0xffffffffu, es_b, 1); es_b += __shfl_xor_sync(0xffffffffu, es_b, 2);
            ed_b += __shfl_xor_sync(0xffffffffu, ed_b, 1); ed_b += __shfl_xor_sync(0xffffffffu, ed_b, 2);
            if (tc == 0) {
                if (r0 < NN) { g_es1[(size_t)r0 * H1 + head] = es_a; g_ed1[(size_t)r0 * H1 + head] = ed_a; }
                if (r1 < NN) { g_es1[(size_t)r1 * H1 + head] = es_b; g_ed1[(size_t)r1 * H1 + head] = ed_b; }
            }
        }
    }
}

// ---------------- fused agg1 + gemm2 + es2/ed2 ----------------
// Block = 8 warps = 8 consecutive dsts. h1act lives only in smem.
__global__ __launch_bounds__(256) void agg1_gemm2_kernel(const float* __restrict__ W2,
                                                         const float* __restrict__ a2s,
                                                         const float* __restrict__ a2d) {
    __shared__ float h1s[8][64];
    __shared__ float Wst[16][68];       // W2 transposed [c][j], padded
    __shared__ float sa2s[CC], sa2d[CC];
    int tid = threadIdx.x, wid = tid >> 5, lane = tid & 31;
    {
        float4 v = ((const float4*)W2)[tid];   // j = tid>>2, c0 = (tid&3)*4
        int j = tid >> 2, c0 = (tid & 3) * 4;
        Wst[c0 + 0][j] = v.x; Wst[c0 + 1][j] = v.y;
        Wst[c0 + 2][j] = v.z; Wst[c0 + 3][j] = v.w;
        if (tid < CC) { sa2s[tid] = a2s[tid]; sa2d[tid] = a2d[tid]; }
    }

    int dst = blockIdx.x * 8 + wid;         // grid = NN/8 exactly
    int myhead = lane >> 2;
    float edv = g_ed1[(size_t)dst * H1 + myhead];
    float m = -INFINITY, s = 0.f;
    float acc0 = 0.f, acc1 = 0.f;
    int beg = g_rowptr[dst], end = g_rowptr[dst + 1];   // >=1 edge (self loop)
    int s0 = g_col[beg];
    int s1 = (beg + 1 < end) ? g_col[beg + 1] : s0;
    float es_c = g_es1[(size_t)s0 * H1 + myhead];
    float2 hv_c = *(const float2*)(g_h1 + (size_t)s0 * HD + lane * 2);
    for (int e = beg; e < end; e++) {
        int s2 = (e + 2 < end) ? g_col[e + 2] : s1;
        float es_n = g_es1[(size_t)s1 * H1 + myhead];
        float2 hv_n = *(const float2*)(g_h1 + (size_t)s1 * HD + lane * 2);
        float ev = es_c + edv;
        ev = ev > 0.f ? ev : 0.2f * ev;
        float nm = fmaxf(m, ev);
        float sc = __expf(m - nm);
        float w  = __expf(ev - nm);
        m = nm;
        s = s * sc + w;
        acc0 = acc0 * sc + hv_c.x * w;
        acc1 = acc1 * sc + hv_c.y * w;
        es_c = es_n; hv_c = hv_n;
        s1 = s2;
    }
    float o0 = acc0 / s;
    float o1 = acc1 / s;
    o0 = o0 > 0.f ? o0 : expm1f(o0);        // ELU
    o1 = o1 > 0.f ? o1 : expm1f(o1);
    h1s[wid][lane * 2] = o0;
    h1s[wid][lane * 2 + 1] = o1;
    __syncthreads();

    // gemm2 for the block's 8 rows: 8 x 64 @ 64 x 16
    if (tid < 128) {
        int nl = tid >> 4, c = tid & 15;
        int n = blockIdx.x * 8 + nl;
        float sum = 0.f;
        #pragma unroll
        for (int j4 = 0; j4 < 16; j4++) {
            float4 hv = *(const float4*)&h1s[nl][j4 * 4];
            float4 wv = *(const float4*)&Wst[c][j4 * 4];
            sum += hv.x * wv.x + hv.y * wv.y + hv.z * wv.z + hv.w * wv.w;
        }
        g_h2[(size_t)n * CC + c] = sum;
        float es = sum * sa2s[c];
        float ed = sum * sa2d[c];
        #pragma unroll
        for (int off = 1; off < 16; off <<= 1) {
            es += __shfl_xor_sync(0xffffffffu, es, off, 16);
            ed += __shfl_xor_sync(0xffffffffu, ed, off, 16);
        }
        if (c == 0) { g_es2[n] = es; g_ed2[n] = ed; }
    }
}

// ---------------- layer-2 aggregation + log_softmax : half-warp/dst, depth-2 prefetch ----------------
__global__ __launch_bounds__(256) void agg2_kernel(float* __restrict__ out) {
    int gw = (blockIdx.x * blockDim.x + threadIdx.x) >> 5;
    int lane = threadIdx.x & 31;
    int half = lane >> 4;
    int r = lane & 15;
    int dst = gw * 2 + half;
    float edv = g_ed2[dst];
    float m = -INFINITY, s = 0.f, acc = 0.f;
    int beg = g_rowptr[dst], end = g_rowptr[dst + 1];
    int s0 = g_col[beg];
    int s1 = (beg + 1 < end) ? g_col[beg + 1] : s0;
    float es_c = g_es2[s0];
    float hv_c = g_h2[(size_t)s0 * CC + r];
    for (int e = beg; e < end; e++) {
        int s2 = (e + 2 < end) ? g_col[e + 2] : s1;
        float es_n = g_es2[s1];
        float hv_n = g_h2[(size_t)s1 * CC + r];
        float ev = es_c + edv;
        ev = ev > 0.f ? ev : 0.2f * ev;
        float nm = fmaxf(m, ev);
        float sc = __expf(m - nm);
        float w  = __expf(ev - nm);
        m = nm;
        s = s * sc + w;
        acc = acc * sc + hv_c * w;
        es_c = es_n; hv_c = hv_n;
        s1 = s2;
    }
    float o = acc / s;
    float mx = o;
    #pragma unroll
    for (int off = 8; off; off >>= 1)
        mx = fmaxf(mx, __shfl_xor_sync(0xffffffffu, mx, off, 16));
    float se = __expf(o - mx);
    #pragma unroll
    for (int off = 8; off; off >>= 1)
        se += __shfl_xor_sync(0xffffffffu, se, off, 16);
    out[(size_t)dst * CC + r] = o - mx - logf(se);
}

// ---------------- launch: fork gemm1 onto a side stream to overlap with CSR build ----------------
extern "C" void kernel_launch(void* const* d_in, const int* in_sizes, int n_in,
                              void* d_out, int out_size) {
    const float* x    = (const float*)d_in[0];
    const void*  ei   = d_in[1];
    const float* W1   = (const float*)d_in[2];
    const float* a1s  = (const float*)d_in[3];
    const float* a1d  = (const float*)d_in[4];
    const float* W2   = (const float*)d_in[5];
    const float* a2s  = (const float*)d_in[6];
    const float* a2d  = (const float*)d_in[7];
    float* out = (float*)d_out;

    static cudaStream_t s2 = nullptr;
    static cudaEvent_t ev_init = nullptr, ev_gemm = nullptr;
    if (!s2) {
        cudaStreamCreateWithFlags(&s2, cudaStreamNonBlocking);
        cudaEventCreateWithFlags(&ev_init, cudaEventDisableTiming);
        cudaEventCreateWithFlags(&ev_gemm, cudaEventDisableTiming);
        cudaFuncSetAttribute(gemm1_mma_kernel, cudaFuncAttributeMaxDynamicSharedMemorySize, G1_SMEM);
    }

    init_kernel<<<NB, 256>>>((const int*)ei, W1);
    cudaEventRecord(ev_init, 0);

    // branch B: gemm1 on side stream (depends only on init's wfrag)
    cudaStreamWaitEvent(s2, ev_init, 0);
    gemm1_mma_kernel<<<(NN + 127) / 128, 256, G1_SMEM, s2>>>(x, a1s, a1d);
    cudaEventRecord(ev_gemm, s2);

    // branch A: CSR build on main stream
    convert_hist_kernel<<<(ET + 255) / 256, 256>>>(ei);
    scan_partial_kernel<<<NB, 256>>>();
    scan_blocks_kernel<<<1, 512>>>();
    scan_apply_kernel<<<NB, 256>>>();
    scatter_kernel<<<(ET + 255) / 256, 256>>>();

    // join
    cudaStreamWaitEvent(0, ev_gemm, 0);
    agg1_gemm2_kernel<<<NN / 8, 256>>>(W2, a2s, a2d);
    agg2_kernel<<<(NN * 16 + 255) / 256, 256>>>(out);
}

// round 16
// speedup vs baseline: 1.2351x; 1.0689x over previous
#include <cuda_runtime.h>
#include <cuda_bf16.h>
#include <math.h>
#include <stdint.h>

#define NN   100000
#define EE   1600000
#define ET   1700000      // EE + NN self loops
#define FIN  512
#define HD   64           // H1*D1
#define H1   8
#define D1   8
#define CC   16
#define NB   ((NN + 255) / 256)   // 391 scan blocks

// ---------------- scratch (static device memory; no allocations) ----------------
__device__ int   g_flag;
__device__ int   g_src[ET];
__device__ int   g_dst[ET];
__device__ int   g_col[ET];
__device__ int   g_counts[NN];
__device__ int   g_cursor[NN];
__device__ int   g_rowptr[NN + 1];
__device__ int   g_bsum[NB];
__device__ int   g_boff[NB];
// W1^T in mma-fragment order with K-permutation: [n][ks][tc] uint4 =
// {hi(kp,kp+1), hi(kp+2,kp+3), lo(kp,kp+1), lo(kp+2,kp+3)}, kp = ks*16 + tc*4
__device__ uint4 g_wfrag[HD * 32 * 4];
__device__ float g_h1[(size_t)NN * HD];
__device__ float g_es1[(size_t)NN * H1];
__device__ float g_ed1[(size_t)NN * H1];
__device__ float g_h2[(size_t)NN * CC];
__device__ float g_es2[NN];
__device__ float g_ed2[NN];

__device__ __forceinline__ uint32_t pack_hi(float v0, float v1) {
    __nv_bfloat16 h0 = __float2bfloat16_rn(v0);
    __nv_bfloat16 h1 = __float2bfloat16_rn(v1);
    return ((uint32_t)__bfloat16_as_ushort(h1) << 16) | __bfloat16_as_ushort(h0);
}
__device__ __forceinline__ uint32_t pack_lo(float v0, float v1) {
    __nv_bfloat16 h0 = __float2bfloat16_rn(v0);
    __nv_bfloat16 h1 = __float2bfloat16_rn(v1);
    __nv_bfloat16 l0 = __float2bfloat16_rn(v0 - __bfloat162float(h0));
    __nv_bfloat16 l1 = __float2bfloat16_rn(v1 - __bfloat162float(h1));
    return ((uint32_t)__bfloat16_as_ushort(l1) << 16) | __bfloat16_as_ushort(l0);
}

// ---------------- init: zero counts + dtype detect + W1 fragment-order convert ----------------
__global__ __launch_bounds__(256) void init_kernel(const int* ei32, const float* __restrict__ W1) {
    int i = blockIdx.x * blockDim.x + threadIdx.x;
    if (i < NN) g_counts[i] = 0;
    if (i < HD * 32 * 4) {                  // 8192 fragments
        int n = i >> 7, ks = (i >> 2) & 31, tc = i & 3;
        int kp = ks * 16 + tc * 4;          // physical k base (K-permuted order)
        float v0 = W1[(size_t)kp * HD + n];
        float v1 = W1[(size_t)(kp + 1) * HD + n];
        float v2 = W1[(size_t)(kp + 2) * HD + n];
        float v3 = W1[(size_t)(kp + 3) * HD + n];
        uint4 w;
        w.x = pack_hi(v0, v1);
        w.y = pack_hi(v2, v3);
        w.z = pack_lo(v0, v1);
        w.w = pack_lo(v2, v3);
        g_wfrag[i] = w;
    }
    if (blockIdx.x == 0 && threadIdx.x < 32) {
        int lane = threadIdx.x;
        int bad = 0;
        for (int j = lane; j < 256; j += 32) {
            int k = j * 6250;
            if (ei32[2 * k + 1] != 0) bad = 1;
        }
        unsigned b = __ballot_sync(0xffffffffu, bad);
        if (lane == 0) g_flag = (b == 0) ? 1 : 0;
    }
}

// ---------------- convert + histogram in one edge pass ----------------
__global__ __launch_bounds__(256) void convert_hist_kernel(const void* ei) {
    int e = blockIdx.x * blockDim.x + threadIdx.x;
    if (e >= ET) return;
    int s, d;
    if (e < EE) {
        if (g_flag) {
            const long long* p = (const long long*)ei;
            s = (int)p[e]; d = (int)p[EE + e];
        } else {
            const int* p = (const int*)ei;
            s = p[e]; d = p[EE + e];
        }
    } else {
        s = e - EE; d = e - EE;
    }
    g_src[e] = s; g_dst[e] = d;
    atomicAdd(&g_counts[d], 1);
}

// ---------------- parallel scan ----------------
__global__ __launch_bounds__(256) void scan_partial_kernel() {
    __shared__ int wsum[8];
    int t = threadIdx.x;
    int i = blockIdx.x * 256 + t;
    int c = (i < NN) ? g_counts[i] : 0;
    int v = c;
    #pragma unroll
    for (int off = 1; off < 32; off <<= 1) v += __shfl_xor_sync(0xffffffffu, v, off);
    if ((t & 31) == 0) wsum[t >> 5] = v;
    __syncthreads();
    if (t == 0) {
        int s = 0;
        #pragma unroll
        for (int w = 0; w < 8; w++) s += wsum[w];
        g_bsum[blockIdx.x] = s;
    }
}

__global__ __launch_bounds__(512) void scan_blocks_kernel() {
    __shared__ int sh[512];
    int t = threadIdx.x;
    sh[t] = (t < NB) ? g_bsum[t] : 0;
    __syncthreads();
    for (int off = 1; off < 512; off <<= 1) {
        int v = (t >= off) ? sh[t - off] : 0;
        __syncthreads();
        sh[t] += v;
        __syncthreads();
    }
    if (t < NB) g_boff[t] = (t == 0) ? 0 : sh[t - 1];
}

__global__ __launch_bounds__(256) void scan_apply_kernel() {
    __shared__ int woff[8];
    int t = threadIdx.x, lane = t & 31, wid = t >> 5;
    int i = blockIdx.x * 256 + t;
    int c = (i < NN) ? g_counts[i] : 0;
    int incl = c;
    #pragma unroll
    for (int off = 1; off < 32; off <<= 1) {
        int v = __shfl_up_sync(0xffffffffu, incl, off);
        if (lane >= off) incl += v;
    }
    if (lane == 31) woff[wid] = incl;
    __syncthreads();
    if (t == 0) {
        int run = 0;
        #pragma unroll
        for (int w = 0; w < 8; w++) { int v = woff[w]; woff[w] = run; run += v; }
    }
    __syncthreads();
    int excl = incl - c + woff[wid] + g_boff[blockIdx.x];
    if (i < NN) { g_rowptr[i] = excl; g_cursor[i] = excl; }
    if (i == NN - 1) g_rowptr[NN] = ET;
}

__global__ __launch_bounds__(256) void scatter_kernel() {
    int e = blockIdx.x * blockDim.x + threadIdx.x;
    if (e < ET) {
        int d = g_dst[e];
        int pos = atomicAdd(&g_cursor[d], 1);
        g_col[pos] = g_src[e];
    }
}

// ---------------- GEMM1: cp.async-staged A + HMMA split-bf16 (K-permuted, 4x2 layout) ----------------
#define BKG   32                  // K per stage
#define NSTG  4                   // stages
#define ASTR  48                  // fp32 stride per A row
#define STAGE_B (128 * ASTR * 4)  // 24576 bytes
#define G1_SMEM (NSTG * STAGE_B)  // 98304 bytes

__device__ __forceinline__ void cp_async_cg(uint32_t saddr, const void* gptr, int srcsz) {
    asm volatile("cp.async.cg.shared.global [%0], [%1], 16, %2;"
                 :: "r"(saddr), "l"(gptr), "r"(srcsz));
}
__device__ __forceinline__ void cp_commit() { asm volatile("cp.async.commit_group;"); }

__device__ __forceinline__ void cvt_pair(float vx, float vy, uint32_t& hi, uint32_t& lo) {
    asm("cvt.rn.bf16x2.f32 %0, %1, %2;" : "=r"(hi) : "f"(vy), "f"(vx));
    float h0 = __uint_as_float(hi << 16);
    float h1 = __uint_as_float(hi & 0xFFFF0000u);
    float r0 = vx - h0, r1 = vy - h1;
    asm("cvt.rn.bf16x2.f32 %0, %1, %2;" : "=r"(lo) : "f"(r1), "f"(r0));
}

__device__ __forceinline__ void mma16816(float* c, const uint32_t* a, uint32_t b0, uint32_t b1) {
    asm volatile(
        "mma.sync.aligned.m16n8k16.row.col.f32.bf16.bf16.f32 "
        "{%0,%1,%2,%3}, {%4,%5,%6,%7}, {%8,%9}, {%0,%1,%2,%3};"
        : "+f"(c[0]), "+f"(c[1]), "+f"(c[2]), "+f"(c[3])
        : "r"(a[0]), "r"(a[1]), "r"(a[2]), "r"(a[3]), "r"(b0), "r"(b1));
}

__global__ __launch_bounds__(256, 2) void gemm1_mma_kernel(const float* __restrict__ x,
                                                           const float* __restrict__ a1s,
                                                           const float* __restrict__ a1d) {
    extern __shared__ float sA[];           // [NSTG][128][ASTR]
    uint32_t sbase;
    asm("{ .reg .u64 t; cvta.to.shared.u64 t, %1; cvt.u32.u64 %0, t; }" : "=r"(sbase) : "l"(sA));

    int tid = threadIdx.x;
    int wid = tid >> 5, lane = tid & 31;
    int g = lane >> 2, tc = lane & 3;
    int wm = wid & 3, wn = wid >> 2;
    int block_row = blockIdx.x * 128;
    int row_base = block_row + wm * 32;

    float acc[2][4][4];
    #pragma unroll
    for (int mt = 0; mt < 2; mt++)
        #pragma unroll
        for (int nt = 0; nt < 4; nt++)
            #pragma unroll
            for (int q = 0; q < 4; q++) acc[mt][nt][q] = 0.f;

    const int NSTEP = FIN / BKG;            // 16

    #pragma unroll
    for (int s = 0; s < NSTG - 1; s++) {    // prologue: 3 stages
        #pragma unroll
        for (int i = 0; i < 4; i++) {
            int idx = tid + 256 * i;
            int row = idx >> 3, c4 = idx & 7;
            int grow = block_row + row;
            uint32_t sa = sbase + (uint32_t)s * STAGE_B + (row * ASTR + c4 * 4) * 4;
            cp_async_cg(sa, x + (size_t)grow * FIN + s * BKG + c4 * 4,
                        (grow < NN) ? 16 : 0);
        }
        cp_commit();
    }

    for (int step = 0; step < NSTEP; step++) {
        int rem = NSTEP - 1 - step;
        if (rem >= 2) { asm volatile("cp.async.wait_group 2;"); }
        else if (rem == 1) { asm volatile("cp.async.wait_group 1;"); }
        else { asm volatile("cp.async.wait_group 0;"); }
        __syncthreads();

        int nxt = step + NSTG - 1;
        if (nxt < NSTEP) {
            int sbuf = nxt & (NSTG - 1);
            #pragma unroll
            for (int i = 0; i < 4; i++) {
                int idx = tid + 256 * i;
                int row = idx >> 3, c4 = idx & 7;
                int grow = block_row + row;
                uint32_t sa = sbase + (uint32_t)sbuf * STAGE_B + (row * ASTR + c4 * 4) * 4;
                cp_async_cg(sa, x + (size_t)grow * FIN + nxt * BKG + c4 * 4,
                            (grow < NN) ? 16 : 0);
            }
            cp_commit();
        }

        const float* sAc = sA + (step & (NSTG - 1)) * 128 * ASTR;
        #pragma unroll
        for (int ks = 0; ks < BKG / 16; ks++) {  // 2
            int ksg = step * 2 + ks;            // global 16-k step index (0..31)
            int kl = ks * 16 + tc * 4;          // physical k base for this thread
            uint32_t ah[2][4], al[2][4];
            #pragma unroll
            for (int mt = 0; mt < 2; mt++) {
                int lr0 = wm * 32 + mt * 16 + g;
                int lr1 = lr0 + 8;
                float4 v0 = *(const float4*)(sAc + lr0 * ASTR + kl);
                float4 v1 = *(const float4*)(sAc + lr1 * ASTR + kl);
                cvt_pair(v0.x, v0.y, ah[mt][0], al[mt][0]);
                cvt_pair(v1.x, v1.y, ah[mt][1], al[mt][1]);
                cvt_pair(v0.z, v0.w, ah[mt][2], al[mt][2]);
                cvt_pair(v1.z, v1.w, ah[mt][3], al[mt][3]);
            }
            #pragma unroll
            for (int nt = 0; nt < 4; nt++) {
                int n = wn * 32 + nt * 8 + g;
                uint4 w = g_wfrag[(n * 32 + ksg) * 4 + tc];   // 1 LDG.128
                #pragma unroll
                for (int mt = 0; mt < 2; mt++) {
                    mma16816(acc[mt][nt], ah[mt], w.x, w.y);
                    mma16816(acc[mt][nt], al[mt], w.x, w.y);
                    mma16816(acc[mt][nt], ah[mt], w.z, w.w);
                }
            }
        }
    }

    // ---- epilogue: write h1, fused es/ed ----
    int col_base = wn * 32;
    #pragma unroll
    for (int mt = 0; mt < 2; mt++) {
        int r0 = row_base + mt * 16 + g;
        int r1 = r0 + 8;
        #pragma unroll
        for (int nt = 0; nt < 4; nt++) {
            int col = col_base + nt * 8 + tc * 2;
            float* c = acc[mt][nt];
            if (r0 < NN) *(float2*)(g_h1 + (size_t)r0 * HD + col) = make_float2(c[0], c[1]);
            if (r1 < NN) *(float2*)(g_h1 + (size_t)r1 * HD + col) = make_float2(c[2], c[3]);
            int head = (col_base >> 3) + nt;
            float as0 = a1s[head * 8 + tc * 2], as1 = a1s[head * 8 + tc * 2 + 1];
            float ad0 = a1d[head * 8 + tc * 2], ad1 = a1d[head * 8 + tc * 2 + 1];
            float es_a = c[0] * as0 + c[1] * as1;
            float ed_a = c[0] * ad0 + c[1] * ad1;
            float es_b = c[2] * as0 + c[3] * as1;
            float ed_b = c[2] * ad0 + c[3] * ad1;
            es_a += __shfl_xor_sync(0xffffffffu, es_a, 1); es_a += __shfl_xor_sync(0xffffffffu, es_a, 2);
            ed_a += __shfl_xor_sync(0xffffffffu, ed_a, 1); ed_a += __shfl_xor_sync(0xffffffffu, ed_a, 2);
            es_b += __shfl_xor_sync(0xffffffffu, es_b, 1); es_b += __shfl_xor_sync(0xffffffffu, es_b, 2);
            ed_b += __shfl_xor_sync(0xffffffffu, ed_b, 1); ed_b += __shfl_xor_sync(0xffffffffu, ed_b, 2);
            if (tc == 0) {
                if (r0 < NN) { g_es1[(size_t)r0 * H1 + head] = es_a; g_ed1[(size_t)r0 * H1 + head] = ed_a; }
                if (r1 < NN) { g_es1[(size_t)r1 * H1 + head] = es_b; g_ed1[(size_t)r1 * H1 + head] = ed_b; }
            }
        }
    }
}

// ---------------- fused agg1 + gemm2 + es2/ed2 (2-stream online softmax) ----------------
// Block = 8 warps = 8 consecutive dsts. h1act lives only in smem.
__global__ __launch_bounds__(256) void agg1_gemm2_kernel(const float* __restrict__ W2,
                                                         const float* __restrict__ a2s,
                                                         const float* __restrict__ a2d) {
    __shared__ float h1s[8][64];
    __shared__ float Wst[16][68];       // W2 transposed [c][j], padded
    __shared__ float sa2s[CC], sa2d[CC];
    int tid = threadIdx.x, wid = tid >> 5, lane = tid & 31;
    {
        float4 v = ((const float4*)W2)[tid];   // j = tid>>2, c0 = (tid&3)*4
        int j = tid >> 2, c0 = (tid & 3) * 4;
        Wst[c0 + 0][j] = v.x; Wst[c0 + 1][j] = v.y;
        Wst[c0 + 2][j] = v.z; Wst[c0 + 3][j] = v.w;
        if (tid < CC) { sa2s[tid] = a2s[tid]; sa2d[tid] = a2d[tid]; }
    }

    int dst = blockIdx.x * 8 + wid;         // grid = NN/8 exactly
    int myhead = lane >> 2;
    float edv = g_ed1[(size_t)dst * H1 + myhead];
    float mA = -INFINITY, sA = 0.f, a0A = 0.f, a1A = 0.f;
    float mB = -INFINITY, sB = 0.f, a0B = 0.f, a1B = 0.f;
    int beg = g_rowptr[dst], end = g_rowptr[dst + 1];   // >=1 edge (self loop)
    int e = beg;
    for (; e + 1 < end; e += 2) {
        int srcA = g_col[e], srcB = g_col[e + 1];
        float esA = g_es1[(size_t)srcA * H1 + myhead];
        float esB = g_es1[(size_t)srcB * H1 + myhead];
        float2 hvA = *(const float2*)(g_h1 + (size_t)srcA * HD + lane * 2);
        float2 hvB = *(const float2*)(g_h1 + (size_t)srcB * HD + lane * 2);
        float evA = esA + edv;
        evA = evA > 0.f ? evA : 0.2f * evA;
        float nmA = fmaxf(mA, evA);
        float scA = __expf(mA - nmA), wA = __expf(evA - nmA);
        mA = nmA; sA = sA * scA + wA;
        a0A = a0A * scA + hvA.x * wA;
        a1A = a1A * scA + hvA.y * wA;
        float evB = esB + edv;
        evB = evB > 0.f ? evB : 0.2f * evB;
        float nmB = fmaxf(mB, evB);
        float scB = __expf(mB - nmB), wB = __expf(evB - nmB);
        mB = nmB; sB = sB * scB + wB;
        a0B = a0B * scB + hvB.x * wB;
        a1B = a1B * scB + hvB.y * wB;
    }
    if (e < end) {
        int srcA = g_col[e];
        float esA = g_es1[(size_t)srcA * H1 + myhead];
        float2 hvA = *(const float2*)(g_h1 + (size_t)srcA * HD + lane * 2);
        float evA = esA + edv;
        evA = evA > 0.f ? evA : 0.2f * evA;
        float nmA = fmaxf(mA, evA);
        float scA = __expf(mA - nmA), wA = __expf(evA - nmA);
        mA = nmA; sA = sA * scA + wA;
        a0A = a0A * scA + hvA.x * wA;
        a1A = a1A * scA + hvA.y * wA;
    }
    // merge streams
    float mm = fmaxf(mA, mB);
    float fA = __expf(mA - mm), fB = (mB == -INFINITY) ? 0.f : __expf(mB - mm);
    float s = sA * fA + sB * fB;
    float o0 = (a0A * fA + a0B * fB) / s;
    float o1 = (a1A * fA + a1B * fB) / s;
    o0 = o0 > 0.f ? o0 : expm1f(o0);        // ELU
    o1 = o1 > 0.f ? o1 : expm1f(o1);
    h1s[wid][lane * 2] = o0;
    h1s[wid][lane * 2 + 1] = o1;
    __syncthreads();

    // gemm2 for the block's 8 rows: 8 x 64 @ 64 x 16
    if (tid < 128) {
        int nl = tid >> 4, c = tid & 15;
        int n = blockIdx.x * 8 + nl;
        float sum = 0.f;
        #pragma unroll
        for (int j4 = 0; j4 < 16; j4++) {
            float4 hv = *(const float4*)&h1s[nl][j4 * 4];
            float4 wv = *(const float4*)&Wst[c][j4 * 4];
            sum += hv.x * wv.x + hv.y * wv.y + hv.z * wv.z + hv.w * wv.w;
        }
        g_h2[(size_t)n * CC + c] = sum;
        float es = sum * sa2s[c];
        float ed = sum * sa2d[c];
        #pragma unroll
        for (int off = 1; off < 16; off <<= 1) {
            es += __shfl_xor_sync(0xffffffffu, es, off, 16);
            ed += __shfl_xor_sync(0xffffffffu, ed, off, 16);
        }
        if (c == 0) { g_es2[n] = es; g_ed2[n] = ed; }
    }
}

// ---------------- layer-2 aggregation + log_softmax : half-warp/dst, 2-stream ----------------
__global__ __launch_bounds__(256) void agg2_kernel(float* __restrict__ out) {
    int gw = (blockIdx.x * blockDim.x + threadIdx.x) >> 5;
    int lane = threadIdx.x & 31;
    int half = lane >> 4;
    int r = lane & 15;
    int dst = gw * 2 + half;
    float edv = g_ed2[dst];
    float mA = -INFINITY, sA = 0.f, accA = 0.f;
    float mB = -INFINITY, sB = 0.f, accB = 0.f;
    int beg = g_rowptr[dst], end = g_rowptr[dst + 1];
    int e = beg;
    for (; e + 1 < end; e += 2) {
        int srcA = g_col[e], srcB = g_col[e + 1];
        float esA = g_es2[srcA], esB = g_es2[srcB];
        float hvA = g_h2[(size_t)srcA * CC + r];
        float hvB = g_h2[(size_t)srcB * CC + r];
        float evA = esA + edv;
        evA = evA > 0.f ? evA : 0.2f * evA;
        float nmA = fmaxf(mA, evA);
        float scA = __expf(mA - nmA), wA = __expf(evA - nmA);
        mA = nmA; sA = sA * scA + wA;
        accA = accA * scA + hvA * wA;
        float evB = esB + edv;
        evB = evB > 0.f ? evB : 0.2f * evB;
        float nmB = fmaxf(mB, evB);
        float scB = __expf(mB - nmB), wB = __expf(evB - nmB);
        mB = nmB; sB = sB * scB + wB;
        accB = accB * scB + hvB * wB;
    }
    if (e < end) {
        int srcA = g_col[e];
        float esA = g_es2[srcA];
        float hvA = g_h2[(size_t)srcA * CC + r];
        float evA = esA + edv;
        evA = evA > 0.f ? evA : 0.2f * evA;
        float nmA = fmaxf(mA, evA);
        float scA = __expf(mA - nmA), wA = __expf(evA - nmA);
        mA = nmA; sA = sA * scA + wA;
        accA = accA * scA + hvA * wA;
    }
    float mm = fmaxf(mA, mB);
    float fA = __expf(mA - mm), fB = (mB == -INFINITY) ? 0.f : __expf(mB - mm);
    float s = sA * fA + sB * fB;
    float o = (accA * fA + accB * fB) / s;
    float mx = o;
    #pragma unroll
    for (int off = 8; off; off >>= 1)
        mx = fmaxf(mx, __shfl_xor_sync(0xffffffffu, mx, off, 16));
    float se = __expf(o - mx);
    #pragma unroll
    for (int off = 8; off; off >>= 1)
        se += __shfl_xor_sync(0xffffffffu, se, off, 16);
    out[(size_t)dst * CC + r] = o - mx - logf(se);
}

// ---------------- launch: fork gemm1 onto a side stream to overlap with CSR build ----------------
extern "C" void kernel_launch(void* const* d_in, const int* in_sizes, int n_in,
                              void* d_out, int out_size) {
    const float* x    = (const float*)d_in[0];
    const void*  ei   = d_in[1];
    const float* W1   = (const float*)d_in[2];
    const float* a1s  = (const float*)d_in[3];
    const float* a1d  = (const float*)d_in[4];
    const float* W2   = (const float*)d_in[5];
    const float* a2s  = (const float*)d_in[6];
    const float* a2d  = (const float*)d_in[7];
    float* out = (float*)d_out;

    static cudaStream_t s2 = nullptr;
    static cudaEvent_t ev_init = nullptr, ev_gemm = nullptr;
    if (!s2) {
        cudaStreamCreateWithFlags(&s2, cudaStreamNonBlocking);
        cudaEventCreateWithFlags(&ev_init, cudaEventDisableTiming);
        cudaEventCreateWithFlags(&ev_gemm, cudaEventDisableTiming);
        cudaFuncSetAttribute(gemm1_mma_kernel, cudaFuncAttributeMaxDynamicSharedMemorySize, G1_SMEM);
    }

    init_kernel<<<NB, 256>>>((const int*)ei, W1);
    cudaEventRecord(ev_init, 0);

    // branch B: gemm1 on side stream (depends only on init's wfrag)
    cudaStreamWaitEvent(s2, ev_init, 0);
    gemm1_mma_kernel<<<(NN + 127) / 128, 256, G1_SMEM, s2>>>(x, a1s, a1d);
    cudaEventRecord(ev_gemm, s2);

    // branch A: CSR build on main stream
    convert_hist_kernel<<<(ET + 255) / 256, 256>>>(ei);
    scan_partial_kernel<<<NB, 256>>>();
    scan_blocks_kernel<<<1, 512>>>();
    scan_apply_kernel<<<NB, 256>>>();
    scatter_kernel<<<(ET + 255) / 256, 256>>>();

    // join
    cudaStreamWaitEvent(0, ev_gemm, 0);
    agg1_gemm2_kernel<<<NN / 8, 256>>>(W2, a2s, a2d);
    agg2_kernel<<<(NN * 16 + 255) / 256, 256>>>(out);
}